// round 17
// baseline (speedup 1.0000x reference)
#include <cuda_runtime.h>
#include <math.h>

#define NB 256      // batch
#define CC 256      // channels
#define TT 64       // time
#define VV 25       // vertices
#define DD 10       // final SPD dim
#define OUTD 64
#define FEATD 100
#define NS 65       // 10 mean-sums + 55 gram upper-tri
#define BPS 32      // blocks per sample in kernel 1

// scratch (allocation-free rule). Coalesced per-block partials [block][NS].
// Every element rewritten every launch -> no zeroing, graph-deterministic.
__device__ float g_P[NB * BPS * NS];     // 2.1 MB, L2-resident

// ---------------------------------------------------------------------------
// Kernel 1: per (n,c) row: temporal mean, project through Wc = W1@W2@W3,
// then block-local reduction of 8 rows' partials -> 65 coalesced stores.
// NEW: row streamed via float4 (512B aligned warp bursts) into a per-warp
// smem staging buffer (2 halves of 3200B); temporal reduce from smem
// (conflict-free LDS). Exact-minimum sector traffic.
// ---------------------------------------------------------------------------
__global__ void __launch_bounds__(256)
meanproj_kernel(const float* __restrict__ x,
                const float* __restrict__ W1,
                const float* __restrict__ W2,
                const float* __restrict__ W3) {
    __shared__ float t15[VV * 15];
    __shared__ float sWc[VV * DD + 32];   // padded so lanes>=10 read safely
    __shared__ float sy8[8][DD];          // this block's 8 projected vectors
    __shared__ __align__(16) float sSt[8][832];   // per-warp staging (+pad)

    const int tid = threadIdx.x;

    // Wc = (W1 @ W2) @ W3 (redundant per block, negligible)
    for (int e = tid; e < VV * 15; e += 256) {
        int i = e / 15, j = e % 15;
        float s = 0.f;
        #pragma unroll
        for (int k = 0; k < 20; k++) s += W1[i * 20 + k] * W2[k * 15 + j];
        t15[e] = s;
    }
    __syncthreads();
    for (int e = tid; e < VV * DD + 32; e += 256) {
        float s = 0.f;
        if (e < VV * DD) {
            int i = e / DD, j = e % DD;
            #pragma unroll
            for (int k = 0; k < 15; k++) s += t15[i * 15 + k] * W3[k * DD + j];
        }
        sWc[e] = s;
    }
    __syncthreads();

    const int warp = tid >> 5, lane = tid & 31;
    const int gw = blockIdx.x * 8 + warp;           // (n,c) row index
    const float* rowp = x + (size_t)gw * (TT * VV); // 6400 B, 128B-aligned

    // temporal mean via smem staging: 2 halves x 800 floats
    float m0 = 0.f, m1 = 0.f, m2 = 0.f, m3 = 0.f;
    #pragma unroll
    for (int h = 0; h < 2; h++) {
        const float4* src = (const float4*)(rowp + h * 800);
        #pragma unroll
        for (int k = 0; k < 7; k++) {
            const int idx = lane + k * 32;
            if (idx < 200) {
                float4 v = __ldcs(&src[idx]);
                *(float4*)&sSt[warp][idx * 4] = v;
            }
        }
        __syncwarp();
        // lane v accumulates x[t][v] over this half's 32 t-steps.
        // addresses t*25+lane: 32 consecutive words across warp -> no
        // bank conflicts; lanes >=25 read in-buffer junk (discarded).
        #pragma unroll
        for (int t = 0; t < 32; t += 4) {
            m0 += sSt[warp][(t + 0) * VV + lane];
            m1 += sSt[warp][(t + 1) * VV + lane];
            m2 += sSt[warp][(t + 2) * VV + lane];
            m3 += sSt[warp][(t + 3) * VV + lane];
        }
        __syncwarp();   // before next half overwrites the buffer
    }
    const float xm = ((m0 + m1) + (m2 + m3)) * (1.0f / TT);

    // y[o] = sum_v xm[v] * Wc[v][o]  via warp broadcasts
    float y = 0.f;
    #pragma unroll
    for (int v = 0; v < VV; v++) {
        float xv = __shfl_sync(0xffffffffu, xm, v);
        y += xv * sWc[v * DD + lane];               // lanes >=10 hit pad
    }
    if (lane < DD) sy8[warp][lane] = y;
    __syncthreads();

    // block-local partials -> 65 coalesced global stores
    if (tid < NS) {
        float s;
        if (tid < DD) {
            s = 0.f;
            #pragma unroll
            for (int c = 0; c < 8; c++) s += sy8[c][tid];
        } else {
            int e = tid - DD, p = 0;
            while (e >= DD - p) { e -= DD - p; p++; }
            int q = p + e;
            s = 0.f;
            #pragma unroll
            for (int c = 0; c < 8; c++) s += sy8[c][p] * sy8[c][q];
        }
        g_P[blockIdx.x * NS + tid] = s;
    }
}

// row (registers) x matrix (smem, rows padded to 16 floats, 16B-aligned)
__device__ __forceinline__ void rowmul(const float* __restrict__ sM,
                                       const float* Prow, float* nP) {
    #pragma unroll
    for (int j = 0; j < DD; j++) nP[j] = 0.f;
    #pragma unroll
    for (int t = 0; t < DD; t++) {
        const float pv = Prow[t];
        const float4* er = (const float4*)&sM[t * 16];
        float4 e0 = er[0], e1 = er[1], e2 = er[2];
        nP[0] += pv * e0.x; nP[1] += pv * e0.y;
        nP[2] += pv * e0.z; nP[3] += pv * e0.w;
        nP[4] += pv * e1.x; nP[5] += pv * e1.y;
        nP[6] += pv * e1.z; nP[7] += pv * e1.w;
        nP[8] += pv * e2.x; nP[9] += pv * e2.y;
    }
}

// ---------------------------------------------------------------------------
// Kernel 2 (unchanged — 8.0us validated): 128 blocks x 64 threads =
// 2 samples/block, ONE wave. fcw/fcb in smem; per-warp partial reduce,
// E = A/s - I, degree-12 Mercator log via Paterson-Stockmeyer, FC.
// ---------------------------------------------------------------------------
__global__ void __launch_bounds__(64)
spd_kernel(const float* __restrict__ fcw, const float* __restrict__ fcb,
           float* __restrict__ out) {
    __shared__ __align__(16) float sF [OUTD * FEATD];   // 25.6 KB
    __shared__ __align__(16) float sE [2][DD * 16];
    __shared__ __align__(16) float sE2[2][DD * 16];
    __shared__ __align__(16) float sE4[2][DD * 16];
    __shared__ float sB [OUTD];
    __shared__ float sS [2][NS];
    __shared__ float sL [2][FEATD];

    const int tid  = threadIdx.x;
    const int wid  = tid >> 5;
    const int lane = tid & 31;
    const int n    = blockIdx.x * 2 + wid;

    // cooperative FC-weight preload (1600 float4, 25 per thread, MLP-rich)
    {
        float4* d4 = (float4*)sF;
        const float4* s4 = (const float4*)fcw;
        #pragma unroll
        for (int e = tid; e < OUTD * FEATD / 4; e += 64) d4[e] = s4[e];
        if (tid < OUTD) sB[tid] = fcb[tid];
    }

    // ---- per-warp: reduce this sample's 32 partial records ----
    const float* gp = g_P + (size_t)n * BPS * NS;
    #pragma unroll
    for (int h = 0; h < 3; h++) {
        const int i = lane + h * 32;
        if (i < NS) {
            float s = 0.f;
            #pragma unroll
            for (int b = 0; b < BPS; b++) s += gp[b * NS + i];
            sS[wid][i] = s;
        }
    }
    __syncwarp();

    // s = tr(A)/10 (all lanes redundantly); A = (G - C m m^T)/(C-1) + 1e-8 I
    float s_tr = 0.f;
    #pragma unroll
    for (int i = 0; i < DD; i++) {
        int idx = DD + 10 * i - (i * (i - 1)) / 2;
        float mi = sS[wid][i] * (1.0f / CC);
        s_tr += sS[wid][idx] - (float)CC * mi * mi;
    }
    s_tr = s_tr * (1.0f / (CC - 1)) * 0.1f + 1e-8f;
    const float inv_s = __fdividef(1.f, s_tr);
    const float logs  = __logf(s_tr);

    // build row li of E = A/s - I (all lanes; lanes>=10 clamp to row 0)
    const int li = (lane < DD) ? lane : 0;
    float Erow[DD];
    {
        const float mi = sS[wid][li] * (1.0f / CC);
        #pragma unroll
        for (int j = 0; j < DD; j++) {
            int p = li < j ? li : j;
            int q = li < j ? j : li;
            int idx = DD + 10 * p - (p * (p - 1)) / 2 + (q - p);
            float mj = sS[wid][j] * (1.0f / CC);
            float a = (sS[wid][idx] - (float)CC * mi * mj) * (1.0f / (CC - 1))
                    + ((li == j) ? 1e-8f : 0.f);
            Erow[j] = a * inv_s - ((li == j) ? 1.f : 0.f);
        }
    }
    if (lane < DD) {
        #pragma unroll
        for (int j = 0; j < DD; j++) sE[wid][lane * 16 + j] = Erow[j];
    }
    __syncwarp();

    // ---- Paterson-Stockmeyer, degree 12, F = E^4 ----
    const float c1 = 1.f,        c2 = -0.5f,       c3 = 1.f / 3.f;
    const float c4 = -0.25f,     c5 = 0.2f,        c6 = -1.f / 6.f;
    const float c7 = 1.f / 7.f,  c8 = -0.125f,     c9 = 1.f / 9.f;
    const float c10 = -0.1f,     c11 = 1.f / 11.f, c12 = -1.f / 12.f;

    float E2row[DD], E3row[DD], E4row[DD], R[DD], T[DD];
    rowmul(sE[wid], Erow, E2row);                 // E^2
    if (lane < DD) {
        #pragma unroll
        for (int j = 0; j < DD; j++) sE2[wid][lane * 16 + j] = E2row[j];
    }
    __syncwarp();
    rowmul(sE[wid],  E2row, E3row);               // E^3 = E^2 * E
    rowmul(sE2[wid], E2row, E4row);               // E^4 = E^2 * E^2 (ILP)
    if (lane < DD) {
        #pragma unroll
        for (int j = 0; j < DD; j++) sE4[wid][lane * 16 + j] = E4row[j];
    }
    __syncwarp();

    // R = c12*F + C2
    #pragma unroll
    for (int j = 0; j < DD; j++)
        R[j] = c12 * E4row[j] + c9 * Erow[j] + c10 * E2row[j]
             + c11 * E3row[j] + ((li == j) ? c8 : 0.f);
    // R = R*F + C1
    rowmul(sE4[wid], R, T);
    #pragma unroll
    for (int j = 0; j < DD; j++)
        R[j] = T[j] + c5 * Erow[j] + c6 * E2row[j] + c7 * E3row[j]
             + ((li == j) ? c4 : 0.f);
    // R = R*F + C0
    rowmul(sE4[wid], R, T);
    #pragma unroll
    for (int j = 0; j < DD; j++)
        R[j] = T[j] + c1 * Erow[j] + c2 * E2row[j] + c3 * E3row[j];

    if (lane < DD) {
        #pragma unroll
        for (int j = 0; j < DD; j++)
            sL[wid][lane * DD + j] = R[j] + ((li == j) ? logs : 0.f);
    }

    // both warps' preload stores + sL must be visible before FC reads sF
    __syncthreads();

    // ---- FC from smem: each lane computes outputs m = lane and lane+32 ----
    #pragma unroll
    for (int h = 0; h < 2; h++) {
        const int mo = lane + h * 32;
        float s = sB[mo];
        const float* wr = sF + mo * FEATD;
        const float* Lr = sL[wid];
        #pragma unroll 10
        for (int f = 0; f < FEATD; f++) s += Lr[f] * wr[f];
        out[n * OUTD + mo] = s;
    }
}

// ---------------------------------------------------------------------------
extern "C" void kernel_launch(void* const* d_in, const int* in_sizes, int n_in,
                              void* d_out, int out_size) {
    const float *x = nullptr, *W1 = nullptr, *W2 = nullptr, *W3 = nullptr;
    const float *fcw = nullptr, *fcb = nullptr;
    for (int i = 0; i < n_in; i++) {
        switch (in_sizes[i]) {
            case NB * CC * TT * VV: x   = (const float*)d_in[i]; break;
            case 500:               W1  = (const float*)d_in[i]; break;
            case 300:               W2  = (const float*)d_in[i]; break;
            case 150:               W3  = (const float*)d_in[i]; break;
            case 6400:              fcw = (const float*)d_in[i]; break;
            case 64:                fcb = (const float*)d_in[i]; break;
            default: break;
        }
    }

    // one warp per (n,c) row: 65536 rows -> 8192 blocks x 8 warps
    meanproj_kernel<<<(NB * CC) / 8, 256>>>(x, W1, W2, W3);

    // 2 samples per block (one warp each): 128 blocks -> single wave
    spd_kernel<<<NB / 2, 64>>>(fcw, fcb, (float*)d_out);
}